// round 14
// baseline (speedup 1.0000x reference)
#include <cuda_runtime.h>
#include <math.h>

#define THREADS 128
#define ROWS_PER_BLOCK 64
#define PASSES 4          // per warp: 4 passes x 4 rows = 16 rows; x4 warps = 64 rows/block
#define D4 128            // 512 floats = 128 float4 per row
#define PI_HALF 1.57079632679489662f

// ---------------- circuit primitives (all compile-time unrolled) ----------------

template<int BIT>
__device__ __forceinline__ void apply_ry(float s[16], float c, float sn) {
    const int M = 1 << BIT;
#pragma unroll
    for (int i = 0; i < 16; ++i) {
        if ((i & M) == 0) {
            float a = s[i], b = s[i | M];
            s[i]     = fmaf(c,  a, -sn * b);
            s[i | M] = fmaf(sn, a,  c  * b);
        }
    }
}

template<int CBIT, int TBIT>
__device__ __forceinline__ void cnot(float s[16]) {
#pragma unroll
    for (int i = 0; i < 16; ++i) {
        if ((i & (1 << CBIT)) != 0 && (i & (1 << TBIT)) == 0) {
            float t = s[i];
            s[i] = s[i | (1 << TBIT)];
            s[i | (1 << TBIT)] = t;
        }
    }
}

// sin/cos for |h| <= pi/4, pure FMA (no MUFU pressure). err < 3e-7 abs.
__device__ __forceinline__ void sincos_half(float h, float& sn, float& cs) {
    float x2 = h * h;
    float p = fmaf(x2, -1.9841270e-4f, 8.3333333e-3f);
    p = fmaf(x2, p, -1.6666667e-1f);
    sn = h * fmaf(x2, p, 1.0f);
    float q = fmaf(x2, 2.4801587e-5f, -1.3888889e-3f);
    q = fmaf(x2, q, 4.1666667e-2f);
    q = fmaf(x2, q, -0.5f);
    cs = fmaf(x2, q, 1.0f);
}

// Accumulate one float4 of a row against the 4 de-interleaved weight float4s.
// (Function, not macro: a macro parameter named like a float4 member silently
// corrupts member accesses via token substitution — that broke round 0.)
__device__ __forceinline__ void accum4(const float4 v,
                                       const float4 wA, const float4 wB,
                                       const float4 wC, const float4 wD,
                                       float& a0, float& a1, float& a2, float& a3) {
    a0 = fmaf(v.x, wA.x, a0); a0 = fmaf(v.y, wB.x, a0);
    a0 = fmaf(v.z, wC.x, a0); a0 = fmaf(v.w, wD.x, a0);
    a1 = fmaf(v.x, wA.y, a1); a1 = fmaf(v.y, wB.y, a1);
    a1 = fmaf(v.z, wC.y, a1); a1 = fmaf(v.w, wD.y, a1);
    a2 = fmaf(v.x, wA.z, a2); a2 = fmaf(v.y, wB.z, a2);
    a2 = fmaf(v.z, wC.z, a2); a2 = fmaf(v.w, wD.z, a2);
    a3 = fmaf(v.x, wA.w, a3); a3 = fmaf(v.y, wB.w, a3);
    a3 = fmaf(v.z, wC.w, a3); a3 = fmaf(v.w, wD.w, a3);
}

#define RED16(v) v += __shfl_xor_sync(0xffffffffu, v, off)

__global__ void __launch_bounds__(THREADS)
qst_fused(const float* __restrict__ input,
          const float* __restrict__ W_pre,
          const float* __restrict__ b_pre,
          const float* __restrict__ q_params,
          const float* __restrict__ W_post,
          const float* __restrict__ b_post,
          float* __restrict__ out, int B)
{
    // W_pre de-interleaved into 4 arrays so warp LDS.128 is conflict-free:
    // sA[k] = W_pre row (4k+0), sB[k] = row (4k+1), ...
    __shared__ float4 sA[D4], sB[D4], sC[D4], sD[D4];
    __shared__ float  s_qc[24], s_qs[24];
    __shared__ float4 s_qin[ROWS_PER_BLOCK];
    __shared__ float  s_wpost[8], s_bpost[2], s_bpre[4];

    const int tid = threadIdx.x;
    {
        const float4* Wp = reinterpret_cast<const float4*>(W_pre);
        sA[tid] = Wp[4 * tid + 0];
        sB[tid] = Wp[4 * tid + 1];
        sC[tid] = Wp[4 * tid + 2];
        sD[tid] = Wp[4 * tid + 3];
    }
    if (tid < 24) { float h = 0.5f * q_params[tid]; s_qc[tid] = cosf(h); s_qs[tid] = sinf(h); }
    if (tid < 8)  s_wpost[tid] = W_post[tid];
    if (tid < 2)  s_bpost[tid] = b_post[tid];
    if (tid < 4)  s_bpre[tid]  = b_pre[tid];
    __syncthreads();

    const int warp = tid >> 5, lane = tid & 31;
    const int rowBase = blockIdx.x * ROWS_PER_BLOCK;
    const float bp0 = s_bpre[0], bp1 = s_bpre[1], bp2 = s_bpre[2], bp3 = s_bpre[3];

    // ---------------- Phase 1: warp-per-row GEMV + tanh -> s_qin ----------------
#pragma unroll 1
    for (int p = 0; p < PASSES; ++p) {
        int r0 = rowBase + warp * 16 + p * 4;
        if (r0 < B) {   // B % 64 == 0 for this problem -> whole 4-row group valid
            const float4* i0 = reinterpret_cast<const float4*>(input) + (size_t)r0 * D4;
            const float4* i1 = i0 + D4;
            const float4* i2 = i1 + D4;
            const float4* i3 = i2 + D4;
            float a00 = 0, a01 = 0, a02 = 0, a03 = 0;
            float a10 = 0, a11 = 0, a12 = 0, a13 = 0;
            float a20 = 0, a21 = 0, a22 = 0, a23 = 0;
            float a30 = 0, a31 = 0, a32 = 0, a33 = 0;
#pragma unroll
            for (int j = 0; j < 4; ++j) {
                int k = j * 32 + lane;
                float4 wA = sA[k], wB = sB[k], wC = sC[k], wD = sD[k];
                float4 v0 = i0[k], v1 = i1[k], v2 = i2[k], v3 = i3[k];
                accum4(v0, wA, wB, wC, wD, a00, a01, a02, a03);
                accum4(v1, wA, wB, wC, wD, a10, a11, a12, a13);
                accum4(v2, wA, wB, wC, wD, a20, a21, a22, a23);
                accum4(v3, wA, wB, wC, wD, a30, a31, a32, a33);
            }
#pragma unroll
            for (int off = 16; off; off >>= 1) {
                RED16(a00); RED16(a01); RED16(a02); RED16(a03);
                RED16(a10); RED16(a11); RED16(a12); RED16(a13);
                RED16(a20); RED16(a21); RED16(a22); RED16(a23);
                RED16(a30); RED16(a31); RED16(a32); RED16(a33);
            }
            if (lane == 0) {
                int l0 = warp * 16 + p * 4;
                s_qin[l0 + 0] = make_float4(tanhf(a00 + bp0) * PI_HALF, tanhf(a01 + bp1) * PI_HALF,
                                            tanhf(a02 + bp2) * PI_HALF, tanhf(a03 + bp3) * PI_HALF);
                s_qin[l0 + 1] = make_float4(tanhf(a10 + bp0) * PI_HALF, tanhf(a11 + bp1) * PI_HALF,
                                            tanhf(a12 + bp2) * PI_HALF, tanhf(a13 + bp3) * PI_HALF);
                s_qin[l0 + 2] = make_float4(tanhf(a20 + bp0) * PI_HALF, tanhf(a21 + bp1) * PI_HALF,
                                            tanhf(a22 + bp2) * PI_HALF, tanhf(a23 + bp3) * PI_HALF);
                s_qin[l0 + 3] = make_float4(tanhf(a30 + bp0) * PI_HALF, tanhf(a31 + bp1) * PI_HALF,
                                            tanhf(a32 + bp2) * PI_HALF, tanhf(a33 + bp3) * PI_HALF);
            }
        }
    }
    __syncthreads();

    // ---------------- Phase 2: thread-per-row 4-qubit circuit (threads 0..63) ----------------
    int row = rowBase + tid;
    if (tid < ROWS_PER_BLOCK && row < B) {
        float4 qin = s_qin[tid];
        float s[16];
#pragma unroll
        for (int i = 0; i < 16; ++i) s[i] = 0.25f;

        float c, sn;
        sincos_half(qin.x * 0.5f, sn, c); apply_ry<3>(s, c, sn);  // wire 0 -> bit 3
        sincos_half(qin.y * 0.5f, sn, c); apply_ry<2>(s, c, sn);
        sincos_half(qin.z * 0.5f, sn, c); apply_ry<1>(s, c, sn);
        sincos_half(qin.w * 0.5f, sn, c); apply_ry<0>(s, c, sn);

#pragma unroll
        for (int k = 0; k < 6; ++k) {
            cnot<3, 2>(s);   // CNOT(0,1)
            cnot<1, 0>(s);   // CNOT(2,3)
            cnot<2, 1>(s);   // CNOT(1,2)
            apply_ry<3>(s, s_qc[4 * k + 0], s_qs[4 * k + 0]);
            apply_ry<2>(s, s_qc[4 * k + 1], s_qs[4 * k + 1]);
            apply_ry<1>(s, s_qc[4 * k + 2], s_qs[4 * k + 2]);
            apply_ry<0>(s, s_qc[4 * k + 3], s_qs[4 * k + 3]);
        }

        float e0 = 0, e1 = 0, e2 = 0, e3 = 0;
#pragma unroll
        for (int i = 0; i < 16; ++i) {
            float pr = s[i] * s[i];
            e0 += (i & 8) ? -pr : pr;
            e1 += (i & 4) ? -pr : pr;
            e2 += (i & 2) ? -pr : pr;
            e3 += (i & 1) ? -pr : pr;
        }

        float o0 = s_bpost[0];
        o0 = fmaf(e0, s_wpost[0], o0); o0 = fmaf(e1, s_wpost[2], o0);
        o0 = fmaf(e2, s_wpost[4], o0); o0 = fmaf(e3, s_wpost[6], o0);
        float o1 = s_bpost[1];
        o1 = fmaf(e0, s_wpost[1], o1); o1 = fmaf(e1, s_wpost[3], o1);
        o1 = fmaf(e2, s_wpost[5], o1); o1 = fmaf(e3, s_wpost[7], o1);

        reinterpret_cast<float2*>(out)[row] = make_float2(o0, o1);
    }
}

extern "C" void kernel_launch(void* const* d_in, const int* in_sizes, int n_in,
                              void* d_out, int out_size) {
    const float* input    = (const float*)d_in[0];
    const float* W_pre    = (const float*)d_in[1];
    const float* b_pre    = (const float*)d_in[2];
    const float* q_params = (const float*)d_in[3];
    const float* W_post   = (const float*)d_in[4];
    const float* b_post   = (const float*)d_in[5];
    int B = in_sizes[0] / 512;
    int grid = (B + ROWS_PER_BLOCK - 1) / ROWS_PER_BLOCK;
    qst_fused<<<grid, THREADS>>>(input, W_pre, b_pre, q_params, W_post, b_post,
                                 (float*)d_out, B);
}

// round 15
// speedup vs baseline: 1.0381x; 1.0381x over previous
#include <cuda_runtime.h>
#include <math.h>

#define THREADS 128
#define ROWS_PER_BLOCK 64
#define PASSES 4          // per warp: 4 passes x 4 rows = 16 rows; x4 warps = 64 rows/block
#define D4 128            // 512 floats = 128 float4 per row
#define PI_HALF 1.57079632679489662f

// ---------------- circuit primitives (all compile-time unrolled) ----------------

template<int BIT>
__device__ __forceinline__ void apply_ry(float s[16], float c, float sn) {
    const int M = 1 << BIT;
#pragma unroll
    for (int i = 0; i < 16; ++i) {
        if ((i & M) == 0) {
            float a = s[i], b = s[i | M];
            s[i]     = fmaf(c,  a, -sn * b);
            s[i | M] = fmaf(sn, a,  c  * b);
        }
    }
}

template<int CBIT, int TBIT>
__device__ __forceinline__ void cnot(float s[16]) {
#pragma unroll
    for (int i = 0; i < 16; ++i) {
        if ((i & (1 << CBIT)) != 0 && (i & (1 << TBIT)) == 0) {
            float t = s[i];
            s[i] = s[i | (1 << TBIT)];
            s[i | (1 << TBIT)] = t;
        }
    }
}

// sin/cos for |h| <= pi/4, pure FMA (no MUFU pressure). err < 3e-7 abs.
__device__ __forceinline__ void sincos_half(float h, float& sn, float& cs) {
    float x2 = h * h;
    float p = fmaf(x2, -1.9841270e-4f, 8.3333333e-3f);
    p = fmaf(x2, p, -1.6666667e-1f);
    sn = h * fmaf(x2, p, 1.0f);
    float q = fmaf(x2, 2.4801587e-5f, -1.3888889e-3f);
    q = fmaf(x2, q, 4.1666667e-2f);
    q = fmaf(x2, q, -0.5f);
    cs = fmaf(x2, q, 1.0f);
}

// Accumulate one float4 of a row against the 4 de-interleaved weight float4s.
// (Function, not macro: a macro parameter named like a float4 member silently
// corrupts member accesses via token substitution — that broke round 0.)
__device__ __forceinline__ void accum4(const float4 v,
                                       const float4 wA, const float4 wB,
                                       const float4 wC, const float4 wD,
                                       float& a0, float& a1, float& a2, float& a3) {
    a0 = fmaf(v.x, wA.x, a0); a0 = fmaf(v.y, wB.x, a0);
    a0 = fmaf(v.z, wC.x, a0); a0 = fmaf(v.w, wD.x, a0);
    a1 = fmaf(v.x, wA.y, a1); a1 = fmaf(v.y, wB.y, a1);
    a1 = fmaf(v.z, wC.y, a1); a1 = fmaf(v.w, wD.y, a1);
    a2 = fmaf(v.x, wA.z, a2); a2 = fmaf(v.y, wB.z, a2);
    a2 = fmaf(v.z, wC.z, a2); a2 = fmaf(v.w, wD.z, a2);
    a3 = fmaf(v.x, wA.w, a3); a3 = fmaf(v.y, wB.w, a3);
    a3 = fmaf(v.z, wC.w, a3); a3 = fmaf(v.w, wD.w, a3);
}

// Packed-butterfly merge: reduces two live values to one. Lanes with (lane&off)
// carry y's partial, lanes without carry x's. Both shfls are unconditional
// (warp-uniform). 16 values cost 16+8+4+2+1 = 31 SHFL vs 80 naive.
__device__ __forceinline__ float mergered(float x, float y, int off, int lane) {
    float tx = __shfl_xor_sync(0xffffffffu, x, off);
    float ty = __shfl_xor_sync(0xffffffffu, y, off);
    return (lane & off) ? (y + ty) : (x + tx);
}

__global__ void __launch_bounds__(THREADS)
qst_fused(const float* __restrict__ input,
          const float* __restrict__ W_pre,
          const float* __restrict__ b_pre,
          const float* __restrict__ q_params,
          const float* __restrict__ W_post,
          const float* __restrict__ b_post,
          float* __restrict__ out, int B)
{
    // W_pre de-interleaved into 4 arrays so warp LDS.128 is conflict-free:
    // sA[k] = W_pre row (4k+0), sB[k] = row (4k+1), ...
    __shared__ float4 sA[D4], sB[D4], sC[D4], sD[D4];
    __shared__ float  s_qc[24], s_qs[24];
    __shared__ float4 s_qin[ROWS_PER_BLOCK];
    __shared__ float  s_wpost[8], s_bpost[2], s_bpre[4];

    const int tid = threadIdx.x;
    {
        const float4* Wp = reinterpret_cast<const float4*>(W_pre);
        sA[tid] = Wp[4 * tid + 0];
        sB[tid] = Wp[4 * tid + 1];
        sC[tid] = Wp[4 * tid + 2];
        sD[tid] = Wp[4 * tid + 3];
    }
    if (tid < 24) { float h = 0.5f * q_params[tid]; s_qc[tid] = cosf(h); s_qs[tid] = sinf(h); }
    if (tid < 8)  s_wpost[tid] = W_post[tid];
    if (tid < 2)  s_bpost[tid] = b_post[tid];
    if (tid < 4)  s_bpre[tid]  = b_pre[tid];
    __syncthreads();

    const int warp = tid >> 5, lane = tid & 31;
    const int rowBase = blockIdx.x * ROWS_PER_BLOCK;

    // ---------------- Phase 1: warp-per-row GEMV + tanh -> s_qin ----------------
#pragma unroll 1
    for (int p = 0; p < PASSES; ++p) {
        int r0 = rowBase + warp * 16 + p * 4;
        if (r0 < B) {   // B % 64 == 0 for this problem -> whole 4-row group valid
            const float4* i0 = reinterpret_cast<const float4*>(input) + (size_t)r0 * D4;
            const float4* i1 = i0 + D4;
            const float4* i2 = i1 + D4;
            const float4* i3 = i2 + D4;
            float a00 = 0, a01 = 0, a02 = 0, a03 = 0;
            float a10 = 0, a11 = 0, a12 = 0, a13 = 0;
            float a20 = 0, a21 = 0, a22 = 0, a23 = 0;
            float a30 = 0, a31 = 0, a32 = 0, a33 = 0;
#pragma unroll
            for (int j = 0; j < 4; ++j) {
                int k = j * 32 + lane;
                float4 wA = sA[k], wB = sB[k], wC = sC[k], wD = sD[k];
                float4 v0 = i0[k], v1 = i1[k], v2 = i2[k], v3 = i3[k];
                accum4(v0, wA, wB, wC, wD, a00, a01, a02, a03);
                accum4(v1, wA, wB, wC, wD, a10, a11, a12, a13);
                accum4(v2, wA, wB, wC, wD, a20, a21, a22, a23);
                accum4(v3, wA, wB, wC, wD, a30, a31, a32, a33);
            }

            // Packed butterfly: j-index = row*4+col; stage off=16 merges j with
            // j+8 (row+2), off=8 -> row+1, off=4 -> col+2, off=2 -> col+1.
            float z0 = mergered(a00, a20, 16, lane);
            float z1 = mergered(a01, a21, 16, lane);
            float z2 = mergered(a02, a22, 16, lane);
            float z3 = mergered(a03, a23, 16, lane);
            float z4 = mergered(a10, a30, 16, lane);
            float z5 = mergered(a11, a31, 16, lane);
            float z6 = mergered(a12, a32, 16, lane);
            float z7 = mergered(a13, a33, 16, lane);

            float w0 = mergered(z0, z4, 8, lane);
            float w1 = mergered(z1, z5, 8, lane);
            float w2 = mergered(z2, z6, 8, lane);
            float w3 = mergered(z3, z7, 8, lane);

            float u0 = mergered(w0, w2, 4, lane);
            float u1 = mergered(w1, w3, 4, lane);

            float t = mergered(u0, u1, 2, lane);
            t += __shfl_xor_sync(0xffffffffu, t, 1);

            // Lane l (even) now holds the FULL sum for row=(l>>3)&3, col=(l>>1)&3.
            // 16 lanes each do one tanh + one scalar STS (16 consecutive floats
            // -> conflict-free) instead of lane 0 doing 16 tanh serially.
            if (!(lane & 1)) {
                int r = (lane >> 3) & 3;
                int c = (lane >> 1) & 3;
                float q = tanhf(t + s_bpre[c]) * PI_HALF;
                reinterpret_cast<float*>(s_qin)[(warp * 16 + p * 4 + r) * 4 + c] = q;
            }
        }
    }
    __syncthreads();

    // ---------------- Phase 2: thread-per-row 4-qubit circuit (threads 0..63) ----------------
    int row = rowBase + tid;
    if (tid < ROWS_PER_BLOCK && row < B) {
        float4 qin = s_qin[tid];
        float s[16];
#pragma unroll
        for (int i = 0; i < 16; ++i) s[i] = 0.25f;

        float c, sn;
        sincos_half(qin.x * 0.5f, sn, c); apply_ry<3>(s, c, sn);  // wire 0 -> bit 3
        sincos_half(qin.y * 0.5f, sn, c); apply_ry<2>(s, c, sn);
        sincos_half(qin.z * 0.5f, sn, c); apply_ry<1>(s, c, sn);
        sincos_half(qin.w * 0.5f, sn, c); apply_ry<0>(s, c, sn);

#pragma unroll
        for (int k = 0; k < 6; ++k) {
            cnot<3, 2>(s);   // CNOT(0,1)
            cnot<1, 0>(s);   // CNOT(2,3)
            cnot<2, 1>(s);   // CNOT(1,2)
            apply_ry<3>(s, s_qc[4 * k + 0], s_qs[4 * k + 0]);
            apply_ry<2>(s, s_qc[4 * k + 1], s_qs[4 * k + 1]);
            apply_ry<1>(s, s_qc[4 * k + 2], s_qs[4 * k + 2]);
            apply_ry<0>(s, s_qc[4 * k + 3], s_qs[4 * k + 3]);
        }

        float e0 = 0, e1 = 0, e2 = 0, e3 = 0;
#pragma unroll
        for (int i = 0; i < 16; ++i) {
            float pr = s[i] * s[i];
            e0 += (i & 8) ? -pr : pr;
            e1 += (i & 4) ? -pr : pr;
            e2 += (i & 2) ? -pr : pr;
            e3 += (i & 1) ? -pr : pr;
        }

        float o0 = s_bpost[0];
        o0 = fmaf(e0, s_wpost[0], o0); o0 = fmaf(e1, s_wpost[2], o0);
        o0 = fmaf(e2, s_wpost[4], o0); o0 = fmaf(e3, s_wpost[6], o0);
        float o1 = s_bpost[1];
        o1 = fmaf(e0, s_wpost[1], o1); o1 = fmaf(e1, s_wpost[3], o1);
        o1 = fmaf(e2, s_wpost[5], o1); o1 = fmaf(e3, s_wpost[7], o1);

        reinterpret_cast<float2*>(out)[row] = make_float2(o0, o1);
    }
}

extern "C" void kernel_launch(void* const* d_in, const int* in_sizes, int n_in,
                              void* d_out, int out_size) {
    const float* input    = (const float*)d_in[0];
    const float* W_pre    = (const float*)d_in[1];
    const float* b_pre    = (const float*)d_in[2];
    const float* q_params = (const float*)d_in[3];
    const float* W_post   = (const float*)d_in[4];
    const float* b_post   = (const float*)d_in[5];
    int B = in_sizes[0] / 512;
    int grid = (B + ROWS_PER_BLOCK - 1) / ROWS_PER_BLOCK;
    qst_fused<<<grid, THREADS>>>(input, W_pre, b_pre, q_params, W_post, b_post,
                                 (float*)d_out, B);
}